// round 8
// baseline (speedup 1.0000x reference)
#include <cuda_runtime.h>
#include <math.h>

#define NN 100000
#define EE 1600000
#define FD 128

// ---------------- scratch (device globals: allocation-free) ----------------
__device__ int   g_off[NN + 1];
__device__ int   g_cur[NN];
__device__ int   g_src[EE];
__device__ float g_attr[EE];
__device__ float g_xsrc[(size_t)NN * FD];
__device__ float g_xdst[(size_t)NN * FD];
__device__ float g_wt[2][128 * 128];   // transposed weights [c][k]

// ---------------- packed f32x2 helpers (sm_103a) ----------------
__device__ __forceinline__ unsigned long long ffma2(unsigned long long a,
                                                    unsigned long long b,
                                                    unsigned long long c) {
    unsigned long long d;
    asm("fma.rn.f32x2 %0, %1, %2, %3;" : "=l"(d) : "l"(a), "l"(b), "l"(c));
    return d;
}
__device__ __forceinline__ float2 upk(unsigned long long v) {
    float lo, hi;
    asm("mov.b64 {%0, %1}, %2;" : "=f"(lo), "=f"(hi) : "l"(v));
    return make_float2(lo, hi);
}

// ---------------- CSR build ----------------
__global__ void k_zero() {
    int i = blockIdx.x * blockDim.x + threadIdx.x;
    if (i < NN) g_cur[i] = 0;
}

__global__ void k_hist(const int* __restrict__ ei) {
    int e = blockIdx.x * blockDim.x + threadIdx.x;
    if (e < EE) atomicAdd(&g_cur[ei[EE + e]], 1);
}

__global__ void k_scan() {
    __shared__ int wsum[32];
    int tid = threadIdx.x, lane = tid & 31, wid = tid >> 5;
    int carry = 0;
    for (int base = 0; base < NN; base += 1024) {
        int i = base + tid;
        int v = (i < NN) ? g_cur[i] : 0;
        int xv = v;
#pragma unroll
        for (int off = 1; off < 32; off <<= 1) {
            int y = __shfl_up_sync(0xffffffffu, xv, off);
            if (lane >= off) xv += y;
        }
        if (lane == 31) wsum[wid] = xv;
        __syncthreads();
        if (wid == 0) {
            int s = wsum[lane];
#pragma unroll
            for (int off = 1; off < 32; off <<= 1) {
                int y = __shfl_up_sync(0xffffffffu, s, off);
                if (lane >= off) s += y;
            }
            wsum[lane] = s;
        }
        __syncthreads();
        int wpre = wid ? wsum[wid - 1] : 0;
        int excl = carry + wpre + xv - v;
        if (i < NN) { g_off[i] = excl; g_cur[i] = excl; }
        carry += wsum[31];
        __syncthreads();
    }
    if (tid == 0) g_off[NN] = carry;
}

__global__ void k_fill(const int* __restrict__ ei, const float* __restrict__ ea) {
    int e = blockIdx.x * blockDim.x + threadIdx.x;
    if (e < EE) {
        int d = ei[EE + e];
        int p = atomicAdd(&g_cur[d], 1);
        g_src[p]  = ei[e];
        g_attr[p] = ea[e];
    }
}

// ---------------- weight transpose: g_wt[m][c*128+k] = W_m[k*128+c] --------
__global__ void k_wt(const float* __restrict__ Ws, const float* __restrict__ Wd) {
    int i = blockIdx.x * blockDim.x + threadIdx.x;
    if (i < 128 * 128) {
        int c = i >> 7, k = i & 127;
        g_wt[0][i] = Ws[k * 128 + c];
        g_wt[1][i] = Wd[k * 128 + c];
    }
}

// ---------------- GEMM: out[i][c] = sum_k x[i][k]*W[k][c] + bias[c] --------
// K-pair vectorized FFMA2: acc holds (even-k, odd-k) partial sums, folded at
// the end. No splat movs. smem rows stride 130 floats -> conflict-free LDS.64.
#define SSTR 130
__global__ __launch_bounds__(256, 1)
void k_gemm_opt(const float* __restrict__ X, const float* __restrict__ Bias,
                int which) {
    extern __shared__ float sm[];
    float* As = sm;                 // [128][SSTR] (row, k)
    float* Bt = sm + 128 * SSTR;    // [128][SSTR] (col, k)
    float* outp = which ? g_xdst : g_xsrc;
    const float* WT = g_wt[which];

    int tid  = threadIdx.x;
    int row0 = blockIdx.x * 128;
    int c4   = (tid & 31) * 4;
    int rr   = tid >> 5;
#pragma unroll
    for (int i = 0; i < 16; i++) {
        int r  = rr + i * 8;
        int gr = row0 + r;
        float4 v = make_float4(0.f, 0.f, 0.f, 0.f);
        if (gr < NN) v = *(const float4*)(X + (size_t)gr * FD + c4);
        *(float2*)(As + r * SSTR + c4)     = make_float2(v.x, v.y);
        *(float2*)(As + r * SSTR + c4 + 2) = make_float2(v.z, v.w);
        float4 w = *(const float4*)(WT + r * 128 + c4);
        *(float2*)(Bt + r * SSTR + c4)     = make_float2(w.x, w.y);
        *(float2*)(Bt + r * SSTR + c4 + 2) = make_float2(w.z, w.w);
    }
    __syncthreads();

    int tx = tid & 15, ty = tid >> 4;     // tx: col base, ty: row group
    int r0 = ty * 8;
    const float* Ab = As + r0 * SSTR;
    const float* Bb = Bt + tx * SSTR;

    unsigned long long acc[8][8];
#pragma unroll
    for (int j = 0; j < 8; j++)
#pragma unroll
        for (int cc = 0; cc < 8; cc++) acc[j][cc] = 0ull;

#pragma unroll 4
    for (int k2 = 0; k2 < 64; k2++) {
        unsigned long long b2[8];
#pragma unroll
        for (int cc = 0; cc < 8; cc++)
            b2[cc] = *(const unsigned long long*)(Bb + cc * 16 * SSTR + 2 * k2);
#pragma unroll
        for (int j = 0; j < 8; j++) {
            unsigned long long a2 = *(const unsigned long long*)(Ab + j * SSTR + 2 * k2);
#pragma unroll
            for (int cc = 0; cc < 8; cc++)
                acc[j][cc] = ffma2(a2, b2[cc], acc[j][cc]);
        }
    }

#pragma unroll
    for (int j = 0; j < 8; j++) {
        int gr = row0 + r0 + j;
        if (gr < NN) {
#pragma unroll
            for (int cc = 0; cc < 8; cc++) {
                int c = tx + 16 * cc;
                float2 p = upk(acc[j][cc]);
                outp[(size_t)gr * FD + c] = p.x + p.y + __ldg(&Bias[c]);
            }
        }
    }
}

// ---------------- fused attention aggregation (one warp per dst node) -------
// Online softmax with single-exp update + 1-deep src-row prefetch.
__global__ void k_agg(const float* __restrict__ x,
                      const float* __restrict__ Wedge,
                      const float* __restrict__ att,
                      const float* __restrict__ bias,
                      const float* __restrict__ gamma,
                      const float* __restrict__ beta,
                      float* __restrict__ out) {
    int node = (int)((blockIdx.x * blockDim.x + threadIdx.x) >> 5);
    int lane = threadIdx.x & 31;
    if (node >= NN) return;

    int beg = g_off[node], end = g_off[node + 1];

    const float4 xd = *(const float4*)(g_xdst + (size_t)node * FD + lane * 4);
    const float4 we = *(const float4*)(Wedge + lane * 4);
    const float4 at = *(const float4*)(att + lane * 4);

    float m = -INFINITY;
    float denom = 0.f;
    float4 acc = make_float4(0.f, 0.f, 0.f, 0.f);

    float  ea0 = 0.f;
    float4 a0  = make_float4(0.f, 0.f, 0.f, 0.f);
    if (beg < end) {
        int s0 = __ldg(&g_src[beg]);
        ea0 = __ldg(&g_attr[beg]);
        a0  = *(const float4*)(g_xsrc + (size_t)s0 * FD + lane * 4);
    }

    for (int p = beg; p < end; p++) {
        float4 a  = a0;
        float  ea = ea0;
        int pn = p + 1;
        if (pn < end) {                      // prefetch next edge's src row
            int s1 = __ldg(&g_src[pn]);
            ea0 = __ldg(&g_attr[pn]);
            a0  = *(const float4*)(g_xsrc + (size_t)s1 * FD + lane * 4);
        }

        float hx = a.x + xd.x + ea * we.x;
        float hy = a.y + xd.y + ea * we.y;
        float hz = a.z + xd.z + ea * we.z;
        float hw = a.w + xd.w + ea * we.w;
        hx = hx > 0.f ? hx : 0.2f * hx;
        hy = hy > 0.f ? hy : 0.2f * hy;
        hz = hz > 0.f ? hz : 0.2f * hz;
        hw = hw > 0.f ? hw : 0.2f * hw;

        float part = hx * at.x + hy * at.y + hz * at.z + hw * at.w;
        part += __shfl_xor_sync(0xffffffffu, part, 1);
        part += __shfl_xor_sync(0xffffffffu, part, 2);   // head logit

        // single-exp online softmax: either sc==1 or w==1
        float d  = part - m;                  // +inf on first edge
        float e  = __expf(-fabsf(d));
        bool  up = d > 0.f;
        float sc = up ? e : 1.f;
        float w  = up ? 1.f : e;
        if (up) m = part;

        denom = denom * sc + w;
        acc.x = acc.x * sc + w * a.x;
        acc.y = acc.y * sc + w * a.y;
        acc.z = acc.z * sc + w * a.z;
        acc.w = acc.w * sc + w * a.w;
    }

    float inv = (denom > 0.f) ? (1.0f / denom) : 0.f;
    const float4 bi = *(const float4*)(bias + lane * 4);
    float4 o;
    o.x = acc.x * inv + bi.x;
    o.y = acc.y * inv + bi.y;
    o.z = acc.z * inv + bi.z;
    o.w = acc.w * inv + bi.w;

    float s1 = o.x + o.y + o.z + o.w;
    float s2 = o.x * o.x + o.y * o.y + o.z * o.z + o.w * o.w;
#pragma unroll
    for (int off = 16; off > 0; off >>= 1) {
        s1 += __shfl_xor_sync(0xffffffffu, s1, off);
        s2 += __shfl_xor_sync(0xffffffffu, s2, off);
    }
    float mu   = s1 * (1.f / 128.f);
    float var  = s2 * (1.f / 128.f) - mu * mu;
    float rstd = rsqrtf(var + 1e-5f);

    const float4 ga = *(const float4*)(gamma + lane * 4);
    const float4 be = *(const float4*)(beta + lane * 4);
    const float4 xi = *(const float4*)(x + (size_t)node * FD + lane * 4);

    float4 r;
    r.x = (o.x - mu) * rstd * ga.x + be.x;
    r.y = (o.y - mu) * rstd * ga.y + be.y;
    r.z = (o.z - mu) * rstd * ga.z + be.z;
    r.w = (o.w - mu) * rstd * ga.w + be.w;
    r.x = (r.x > 0.f ? r.x : __expf(r.x) - 1.f) + xi.x;
    r.y = (r.y > 0.f ? r.y : __expf(r.y) - 1.f) + xi.y;
    r.z = (r.z > 0.f ? r.z : __expf(r.z) - 1.f) + xi.z;
    r.w = (r.w > 0.f ? r.w : __expf(r.w) - 1.f) + xi.w;

    *(float4*)(out + (size_t)node * FD + lane * 4) = r;
}

// ---------------- launch ----------------
extern "C" void kernel_launch(void* const* d_in, const int* in_sizes, int n_in,
                              void* d_out, int out_size) {
    const float* x    = (const float*)d_in[0];
    const int*   ei   = (const int*)  d_in[1];
    const float* ea   = (const float*)d_in[2];
    const float* Wsrc = (const float*)d_in[3];
    const float* bsrc = (const float*)d_in[4];
    const float* Wdst = (const float*)d_in[5];
    const float* bdst = (const float*)d_in[6];
    const float* Wed  = (const float*)d_in[7];
    const float* att  = (const float*)d_in[8];
    const float* bias = (const float*)d_in[9];
    const float* gam  = (const float*)d_in[10];
    const float* bet  = (const float*)d_in[11];
    float* out = (float*)d_out;

    const int smem = 2 * 128 * SSTR * sizeof(float);   // 133120 B
    cudaFuncSetAttribute(k_gemm_opt, cudaFuncAttributeMaxDynamicSharedMemorySize, smem);

    k_zero<<<(NN + 255) / 256, 256>>>();
    k_hist<<<(EE + 255) / 256, 256>>>(ei);
    k_wt  <<<(128 * 128 + 255) / 256, 256>>>(Wsrc, Wdst);
    k_scan<<<1, 1024>>>();
    k_fill<<<(EE + 255) / 256, 256>>>(ei, ea);
    k_gemm_opt<<<(NN + 127) / 128, 256, smem>>>(x, bsrc, 0);
    k_gemm_opt<<<(NN + 127) / 128, 256, smem>>>(x, bdst, 1);
    k_agg<<<(NN + 7) / 8, 256>>>(x, Wed, att, bias, gam, bet, out);
}

// round 10
// speedup vs baseline: 1.1715x; 1.1715x over previous
#include <cuda_runtime.h>
#include <math.h>

#define NN 100000
#define EE 1600000
#define FD 128
#define NB 98   // ceil(NN/1024)

// ---------------- scratch (device globals: allocation-free) ----------------
__device__ int   g_off[NN + 1];
__device__ int   g_cur[NN];
__device__ int   g_bsum[NB];
__device__ int   g_boff[NB];
__device__ int   g_src[EE];
__device__ float g_attr[EE];
__device__ float g_xsrc[(size_t)NN * FD];
__device__ float g_xdst[(size_t)NN * FD];
__device__ float g_wt[2][128 * 128];   // transposed weights [c][k]

// ---------------- packed f32x2 helpers (sm_103a) ----------------
__device__ __forceinline__ unsigned long long ffma2(unsigned long long a,
                                                    unsigned long long b,
                                                    unsigned long long c) {
    unsigned long long d;
    asm("fma.rn.f32x2 %0, %1, %2, %3;" : "=l"(d) : "l"(a), "l"(b), "l"(c));
    return d;
}
__device__ __forceinline__ float2 upk(unsigned long long v) {
    float lo, hi;
    asm("mov.b64 {%0, %1}, %2;" : "=f"(lo), "=f"(hi) : "l"(v));
    return make_float2(lo, hi);
}

// ---------------- CSR build ----------------
__global__ void k_zero() {
    int i = blockIdx.x * blockDim.x + threadIdx.x;
    if (i < NN) g_cur[i] = 0;
}

__global__ void k_hist(const int* __restrict__ ei) {
    int e = blockIdx.x * blockDim.x + threadIdx.x;
    if (e < EE) atomicAdd(&g_cur[ei[EE + e]], 1);
}

// ------- multi-block exclusive scan (3 kernels, replaces serial k_scan) ----
__global__ void k_scan1() {
    __shared__ int wsum[32];
    int tid = threadIdx.x, lane = tid & 31, wid = tid >> 5;
    int i = blockIdx.x * 1024 + tid;
    int v = (i < NN) ? g_cur[i] : 0;
    int xv = v;
#pragma unroll
    for (int off = 1; off < 32; off <<= 1) {
        int y = __shfl_up_sync(0xffffffffu, xv, off);
        if (lane >= off) xv += y;
    }
    if (lane == 31) wsum[wid] = xv;
    __syncthreads();
    if (wid == 0) {
        int s = wsum[lane];
#pragma unroll
        for (int off = 1; off < 32; off <<= 1) {
            int y = __shfl_up_sync(0xffffffffu, s, off);
            if (lane >= off) s += y;
        }
        wsum[lane] = s;
    }
    __syncthreads();
    int excl = (wid ? wsum[wid - 1] : 0) + xv - v;
    if (i < NN) g_off[i] = excl;
    if (tid == 0) g_bsum[blockIdx.x] = wsum[31];
}

__global__ void k_scan2() {
    __shared__ int ws[4];
    __shared__ int tot;
    int tid = threadIdx.x, lane = tid & 31, wid = tid >> 5;
    int v = (tid < NB) ? g_bsum[tid] : 0;
    int xv = v;
#pragma unroll
    for (int off = 1; off < 32; off <<= 1) {
        int y = __shfl_up_sync(0xffffffffu, xv, off);
        if (lane >= off) xv += y;
    }
    if (lane == 31) ws[wid] = xv;
    __syncthreads();
    if (tid == 0) {
        int c = 0;
#pragma unroll
        for (int w = 0; w < 4; w++) { int t = ws[w]; ws[w] = c; c += t; }
        tot = c;
    }
    __syncthreads();
    int excl = ws[wid] + xv - v;
    if (tid < NB) g_boff[tid] = excl;
    if (tid == 0) g_off[NN] = tot;
}

__global__ void k_scan3() {
    int i = blockIdx.x * blockDim.x + threadIdx.x;
    if (i < NN) {
        int o = g_off[i] + g_boff[i >> 10];
        g_off[i] = o;
        g_cur[i] = o;
    }
}

__global__ void k_fill(const int* __restrict__ ei, const float* __restrict__ ea) {
    int e = blockIdx.x * blockDim.x + threadIdx.x;
    if (e < EE) {
        int d = ei[EE + e];
        int p = atomicAdd(&g_cur[d], 1);
        g_src[p]  = ei[e];
        g_attr[p] = ea[e];
    }
}

// ---------------- weight transpose: g_wt[m][c*128+k] = W_m[k*128+c] --------
__global__ void k_wt(const float* __restrict__ Ws, const float* __restrict__ Wd) {
    int i = blockIdx.x * blockDim.x + threadIdx.x;
    if (i < 128 * 128) {
        int c = i >> 7, k = i & 127;
        g_wt[0][i] = Ws[k * 128 + c];
        g_wt[1][i] = Wd[k * 128 + c];
    }
}

// ---------------- GEMM: out[i][c] = sum_k x[i][k]*W[k][c] + bias[c] --------
// K-pair vectorized FFMA2: acc holds (even-k, odd-k) partial sums, folded at
// the end. No splat movs. smem rows stride 130 floats -> conflict-free LDS.64.
#define SSTR 130
__global__ __launch_bounds__(256, 1)
void k_gemm_opt(const float* __restrict__ X, const float* __restrict__ Bias,
                int which) {
    extern __shared__ float sm[];
    float* As = sm;                 // [128][SSTR] (row, k)
    float* Bt = sm + 128 * SSTR;    // [128][SSTR] (col, k)
    float* outp = which ? g_xdst : g_xsrc;
    const float* WT = g_wt[which];

    int tid  = threadIdx.x;
    int row0 = blockIdx.x * 128;
    int c4   = (tid & 31) * 4;
    int rr   = tid >> 5;
#pragma unroll
    for (int i = 0; i < 16; i++) {
        int r  = rr + i * 8;
        int gr = row0 + r;
        float4 v = make_float4(0.f, 0.f, 0.f, 0.f);
        if (gr < NN) v = *(const float4*)(X + (size_t)gr * FD + c4);
        *(float2*)(As + r * SSTR + c4)     = make_float2(v.x, v.y);
        *(float2*)(As + r * SSTR + c4 + 2) = make_float2(v.z, v.w);
        float4 w = *(const float4*)(WT + r * 128 + c4);
        *(float2*)(Bt + r * SSTR + c4)     = make_float2(w.x, w.y);
        *(float2*)(Bt + r * SSTR + c4 + 2) = make_float2(w.z, w.w);
    }
    __syncthreads();

    int tx = tid & 15, ty = tid >> 4;     // tx: col base, ty: row group
    int r0 = ty * 8;
    const float* Ab = As + r0 * SSTR;
    const float* Bb = Bt + tx * SSTR;

    unsigned long long acc[8][8];
#pragma unroll
    for (int j = 0; j < 8; j++)
#pragma unroll
        for (int cc = 0; cc < 8; cc++) acc[j][cc] = 0ull;

#pragma unroll 4
    for (int k2 = 0; k2 < 64; k2++) {
        unsigned long long b2[8];
#pragma unroll
        for (int cc = 0; cc < 8; cc++)
            b2[cc] = *(const unsigned long long*)(Bb + cc * 16 * SSTR + 2 * k2);
#pragma unroll
        for (int j = 0; j < 8; j++) {
            unsigned long long a2 = *(const unsigned long long*)(Ab + j * SSTR + 2 * k2);
#pragma unroll
            for (int cc = 0; cc < 8; cc++)
                acc[j][cc] = ffma2(a2, b2[cc], acc[j][cc]);
        }
    }

#pragma unroll
    for (int j = 0; j < 8; j++) {
        int gr = row0 + r0 + j;
        if (gr < NN) {
#pragma unroll
            for (int cc = 0; cc < 8; cc++) {
                int c = tx + 16 * cc;
                float2 p = upk(acc[j][cc]);
                outp[(size_t)gr * FD + c] = p.x + p.y + __ldg(&Bias[c]);
            }
        }
    }
}

// ---------------- fused attention aggregation (one warp per dst node) -------
// Online softmax with single-exp update + 1-deep src-row prefetch.
__global__ void k_agg(const float* __restrict__ x,
                      const float* __restrict__ Wedge,
                      const float* __restrict__ att,
                      const float* __restrict__ bias,
                      const float* __restrict__ gamma,
                      const float* __restrict__ beta,
                      float* __restrict__ out) {
    int node = (int)((blockIdx.x * blockDim.x + threadIdx.x) >> 5);
    int lane = threadIdx.x & 31;
    if (node >= NN) return;

    int beg = g_off[node], end = g_off[node + 1];

    const float4 xd = *(const float4*)(g_xdst + (size_t)node * FD + lane * 4);
    const float4 we = *(const float4*)(Wedge + lane * 4);
    const float4 at = *(const float4*)(att + lane * 4);

    float m = -INFINITY;
    float denom = 0.f;
    float4 acc = make_float4(0.f, 0.f, 0.f, 0.f);

    float  ea0 = 0.f;
    float4 a0  = make_float4(0.f, 0.f, 0.f, 0.f);
    if (beg < end) {
        int s0 = __ldg(&g_src[beg]);
        ea0 = __ldg(&g_attr[beg]);
        a0  = *(const float4*)(g_xsrc + (size_t)s0 * FD + lane * 4);
    }

    for (int p = beg; p < end; p++) {
        float4 a  = a0;
        float  ea = ea0;
        int pn = p + 1;
        if (pn < end) {                      // prefetch next edge's src row
            int s1 = __ldg(&g_src[pn]);
            ea0 = __ldg(&g_attr[pn]);
            a0  = *(const float4*)(g_xsrc + (size_t)s1 * FD + lane * 4);
        }

        float hx = a.x + xd.x + ea * we.x;
        float hy = a.y + xd.y + ea * we.y;
        float hz = a.z + xd.z + ea * we.z;
        float hw = a.w + xd.w + ea * we.w;
        hx = hx > 0.f ? hx : 0.2f * hx;
        hy = hy > 0.f ? hy : 0.2f * hy;
        hz = hz > 0.f ? hz : 0.2f * hz;
        hw = hw > 0.f ? hw : 0.2f * hw;

        float part = hx * at.x + hy * at.y + hz * at.z + hw * at.w;
        part += __shfl_xor_sync(0xffffffffu, part, 1);
        part += __shfl_xor_sync(0xffffffffu, part, 2);   // head logit

        // single-exp online softmax: either sc==1 or w==1
        float d  = part - m;                  // +inf on first edge
        float e  = __expf(-fabsf(d));
        bool  up = d > 0.f;
        float sc = up ? e : 1.f;
        float w  = up ? 1.f : e;
        if (up) m = part;

        denom = denom * sc + w;
        acc.x = acc.x * sc + w * a.x;
        acc.y = acc.y * sc + w * a.y;
        acc.z = acc.z * sc + w * a.z;
        acc.w = acc.w * sc + w * a.w;
    }

    float inv = (denom > 0.f) ? (1.0f / denom) : 0.f;
    const float4 bi = *(const float4*)(bias + lane * 4);
    float4 o;
    o.x = acc.x * inv + bi.x;
    o.y = acc.y * inv + bi.y;
    o.z = acc.z * inv + bi.z;
    o.w = acc.w * inv + bi.w;

    float s1 = o.x + o.y + o.z + o.w;
    float s2 = o.x * o.x + o.y * o.y + o.z * o.z + o.w * o.w;
#pragma unroll
    for (int off = 16; off > 0; off >>= 1) {
        s1 += __shfl_xor_sync(0xffffffffu, s1, off);
        s2 += __shfl_xor_sync(0xffffffffu, s2, off);
    }
    float mu   = s1 * (1.f / 128.f);
    float var  = s2 * (1.f / 128.f) - mu * mu;
    float rstd = rsqrtf(var + 1e-5f);

    const float4 ga = *(const float4*)(gamma + lane * 4);
    const float4 be = *(const float4*)(beta + lane * 4);
    const float4 xi = *(const float4*)(x + (size_t)node * FD + lane * 4);

    float4 r;
    r.x = (o.x - mu) * rstd * ga.x + be.x;
    r.y = (o.y - mu) * rstd * ga.y + be.y;
    r.z = (o.z - mu) * rstd * ga.z + be.z;
    r.w = (o.w - mu) * rstd * ga.w + be.w;
    r.x = (r.x > 0.f ? r.x : __expf(r.x) - 1.f) + xi.x;
    r.y = (r.y > 0.f ? r.y : __expf(r.y) - 1.f) + xi.y;
    r.z = (r.z > 0.f ? r.z : __expf(r.z) - 1.f) + xi.z;
    r.w = (r.w > 0.f ? r.w : __expf(r.w) - 1.f) + xi.w;

    *(float4*)(out + (size_t)node * FD + lane * 4) = r;
}

// ---------------- launch ----------------
extern "C" void kernel_launch(void* const* d_in, const int* in_sizes, int n_in,
                              void* d_out, int out_size) {
    const float* x    = (const float*)d_in[0];
    const int*   ei   = (const int*)  d_in[1];
    const float* ea   = (const float*)d_in[2];
    const float* Wsrc = (const float*)d_in[3];
    const float* bsrc = (const float*)d_in[4];
    const float* Wdst = (const float*)d_in[5];
    const float* bdst = (const float*)d_in[6];
    const float* Wed  = (const float*)d_in[7];
    const float* att  = (const float*)d_in[8];
    const float* bias = (const float*)d_in[9];
    const float* gam  = (const float*)d_in[10];
    const float* bet  = (const float*)d_in[11];
    float* out = (float*)d_out;

    const int smem = 2 * 128 * SSTR * sizeof(float);   // 133120 B
    cudaFuncSetAttribute(k_gemm_opt, cudaFuncAttributeMaxDynamicSharedMemorySize, smem);

    k_zero<<<(NN + 255) / 256, 256>>>();
    k_hist<<<(EE + 255) / 256, 256>>>(ei);
    k_wt  <<<(128 * 128 + 255) / 256, 256>>>(Wsrc, Wdst);
    k_scan1<<<NB, 1024>>>();
    k_scan2<<<1, 128>>>();
    k_scan3<<<(NN + 255) / 256, 256>>>();
    k_fill<<<(EE + 255) / 256, 256>>>(ei, ea);
    k_gemm_opt<<<(NN + 127) / 128, 256, smem>>>(x, bsrc, 0);
    k_gemm_opt<<<(NN + 127) / 128, 256, smem>>>(x, bdst, 1);
    k_agg<<<(NN + 7) / 8, 256>>>(x, Wed, att, bias, gam, bet, out);
}